// round 1
// baseline (speedup 1.0000x reference)
#include <cuda_runtime.h>
#include <cuda_bf16.h>

// The reference network mathematically collapses: the GNN "layernorm" is taken
// over a feature axis of size 1, so (y - mean)/sqrt(var+eps) == 0 exactly and
// h == ln_bias[l] after every propagation layer, independent of everything
// upstream (hash grids, SIREN trunk, member heads, all 2M edges).
// Final output = softplus(ln_bias[1,0]) * sigmoid((1 - psi_n) * 50), elementwise.
//
// Input order (metadata.txt):
//  0 R_flat, 1 Z_flat, 2 psi_n, 3 bpol_n, 4 ew, 5 ndeg, 6 coord_tables,
//  7 field_tables, 8 so2_W, 9 so2_b, 10 om1, 11 W1, 12 b1, 13 om2, 14 W2,
// 15 b2, 16 mem_W1, 17 mem_b1, 18 mem_W2, 19 mem_b2, 20 pW1, 21 pb1,
// 22 pW2, 23 pb2, 24 ln_scale, 25 ln_bias, 26 esrc, 27 edst

__global__ void collapsed_forward_kernel(const float* __restrict__ psi_n,
                                         const float* __restrict__ ln_bias,
                                         float* __restrict__ out,
                                         int n4) {
    int i = blockIdx.x * blockDim.x + threadIdx.x;
    if (i >= n4) return;

    // refined = softplus(ln_bias[1]); constant, 2 flops per thread — cheaper
    // than a separate broadcast kernel or an extra launch.
    float b = ln_bias[1];
    float refined = log1pf(expf(b));

    float4 p = reinterpret_cast<const float4*>(psi_n)[i];

    float4 r;
    {
        float x = (1.0f - p.x) * 50.0f;
        r.x = refined / (1.0f + expf(-x));
        x = (1.0f - p.y) * 50.0f;
        r.y = refined / (1.0f + expf(-x));
        x = (1.0f - p.z) * 50.0f;
        r.z = refined / (1.0f + expf(-x));
        x = (1.0f - p.w) * 50.0f;
        r.w = refined / (1.0f + expf(-x));
    }
    reinterpret_cast<float4*>(out)[i] = r;
}

extern "C" void kernel_launch(void* const* d_in, const int* in_sizes, int n_in,
                              void* d_out, int out_size) {
    const float* psi_n   = (const float*)d_in[2];
    const float* ln_bias = (const float*)d_in[25];
    float* out = (float*)d_out;

    int n = out_size;           // 65536
    int n4 = n / 4;             // 16384 float4s
    int threads = 256;
    int blocks = (n4 + threads - 1) / threads;  // 64
    collapsed_forward_kernel<<<blocks, threads>>>(psi_n, ln_bias, out, n4);
}

// round 2
// speedup vs baseline: 1.0047x; 1.0047x over previous
#include <cuda_runtime.h>
#include <cuda_bf16.h>

// The reference network mathematically collapses: the GNN "layernorm" is taken
// over a feature axis of size 1, so (y - mean)/sqrt(var+eps) == 0 exactly and
// h == ln_bias[l] after every propagation layer, independent of everything
// upstream (hash grids, SIREN trunk, member heads, all 2M edges of message
// passing).
// Final output = softplus(ln_bias[1,0]) * sigmoid((1 - psi_n) * 50), elementwise.
//
// R2: fast-math intrinsics (__expf / __fdividef) replace the IEEE expf
// software sequences; per-thread instruction count ~3x lower. Accuracy impact
// ~1e-6 rel, vs a 1e-3 gate.

__global__ void collapsed_forward_kernel(const float* __restrict__ psi_n,
                                         const float* __restrict__ ln_bias,
                                         float* __restrict__ out,
                                         int n4) {
    int i = blockIdx.x * blockDim.x + threadIdx.x;
    if (i >= n4) return;

    // Issue both loads immediately so their DRAM latencies overlap.
    float4 p = reinterpret_cast<const float4*>(psi_n)[i];
    float b = __ldg(&ln_bias[1]);

    // softplus(b) — constant per launch, 3 fast instrs per thread.
    float refined = __logf(1.0f + __expf(b));

    float4 r;
    r.x = __fdividef(refined, 1.0f + __expf(fmaf(p.x, 50.0f, -50.0f)));
    r.y = __fdividef(refined, 1.0f + __expf(fmaf(p.y, 50.0f, -50.0f)));
    r.z = __fdividef(refined, 1.0f + __expf(fmaf(p.z, 50.0f, -50.0f)));
    r.w = __fdividef(refined, 1.0f + __expf(fmaf(p.w, 50.0f, -50.0f)));
    reinterpret_cast<float4*>(out)[i] = r;
}

extern "C" void kernel_launch(void* const* d_in, const int* in_sizes, int n_in,
                              void* d_out, int out_size) {
    const float* psi_n   = (const float*)d_in[2];
    const float* ln_bias = (const float*)d_in[25];
    float* out = (float*)d_out;

    int n4 = out_size / 4;      // 16384 float4s
    int threads = 256;
    int blocks = (n4 + threads - 1) / threads;  // 64
    collapsed_forward_kernel<<<blocks, threads>>>(psi_n, ln_bias, out, n4);
}

// round 3
// speedup vs baseline: 1.5000x; 1.4931x over previous
#include <cuda_runtime.h>
#include <cuda_bf16.h>

// The reference network mathematically collapses: the GNN "layernorm" is over
// a feature axis of size 1, so (y - mean)/sqrt(var+eps) == 0 exactly and
// h == ln_bias[l] after each propagation layer, independent of everything
// upstream (hash grids, SIREN trunk, member heads, all 2M edges).
// Output = softplus(ln_bias[1,0]) * sigmoid((1 - psi_n) * 50), elementwise.
//
// R3: latency-shaping only (all pipes ~0% in ncu; kernel is launch+DRAM
// latency bound).
//  - 128 CTAs x 128 thr (was 64x256): covers 128 SMs instead of 64, halving
//    per-SM warp issue/drain serialization.
//  - sigmoid via tanh: refined*sigmoid(x) = 0.5*refined*tanh(x/2) + 0.5*refined
//    -> one MUFU.TANH per element instead of EX2 + RCP.
//  - exact grid, no bounds check; __launch_bounds__ to pin regs.

__global__ __launch_bounds__(128, 1)
void collapsed_forward_kernel(const float* __restrict__ psi_n,
                              const float* __restrict__ ln_bias,
                              float* __restrict__ out) {
    int i = blockIdx.x * 128 + threadIdx.x;   // exactly 16384 threads = n/4

    float4 p = reinterpret_cast<const float4*>(psi_n)[i];
    float b = __ldg(&ln_bias[1]);

    float half_ref = 0.5f * __logf(1.0f + __expf(b));   // 0.5*softplus(b)

    // refined * sigmoid((1-p)*50) = half_ref * tanh(25 - 25p) + half_ref
    float4 r;
    r.x = fmaf(half_ref, tanhf(fmaf(p.x, -25.0f, 25.0f)), half_ref);
    r.y = fmaf(half_ref, tanhf(fmaf(p.y, -25.0f, 25.0f)), half_ref);
    r.z = fmaf(half_ref, tanhf(fmaf(p.z, -25.0f, 25.0f)), half_ref);
    r.w = fmaf(half_ref, tanhf(fmaf(p.w, -25.0f, 25.0f)), half_ref);
    reinterpret_cast<float4*>(out)[i] = r;
}

extern "C" void kernel_launch(void* const* d_in, const int* in_sizes, int n_in,
                              void* d_out, int out_size) {
    const float* psi_n   = (const float*)d_in[2];
    const float* ln_bias = (const float*)d_in[25];
    float* out = (float*)d_out;

    int n4 = out_size / 4;          // 16384
    int blocks = n4 / 128;          // 128 CTAs x 128 threads, exact cover
    collapsed_forward_kernel<<<blocks, 128>>>(psi_n, ln_bias, out);
}

// round 4
// speedup vs baseline: 1.5105x; 1.0070x over previous
#include <cuda_runtime.h>
#include <cuda_bf16.h>

// The reference network mathematically collapses: the GNN "layernorm" is over
// a feature axis of size 1, so (y - mean)/sqrt(var+eps) == 0 exactly and
// h == ln_bias[l] after each propagation layer, independent of everything
// upstream (hash grids, SIREN trunk, member heads, all 2M edges).
// Output = softplus(ln_bias[1,0]) * sigmoid((1 - psi_n) * 50), elementwise.
//
// R4 = best-of-measured combination:
//  - grid 128 CTAs x 128 thr, exact cover, no bounds branch (R3's win)
//  - sigmoid via __expf + __fdividef (R2's fastest kernel body: 4.096us, 16 regs;
//    tanhf variant was 4.288us / 22 regs because tanhf lowers to a branchy
//    software sequence, not bare MUFU.TANH)
// Kernel is pure latency (all ncu pipes ~0%); this is the single-launch floor.

__global__ __launch_bounds__(128, 1)
void collapsed_forward_kernel(const float* __restrict__ psi_n,
                              const float* __restrict__ ln_bias,
                              float* __restrict__ out) {
    int i = blockIdx.x * 128 + threadIdx.x;   // exactly 16384 threads = n/4

    // Issue both loads immediately so their DRAM latencies overlap.
    float4 p = reinterpret_cast<const float4*>(psi_n)[i];
    float b = __ldg(&ln_bias[1]);

    float refined = __logf(1.0f + __expf(b));   // softplus(ln_bias[1])

    // refined * sigmoid((1-p)*50);  (1-p)*50 = fma(p, -50, 50); sigmoid arg negated.
    float4 r;
    r.x = __fdividef(refined, 1.0f + __expf(fmaf(p.x, 50.0f, -50.0f)));
    r.y = __fdividef(refined, 1.0f + __expf(fmaf(p.y, 50.0f, -50.0f)));
    r.z = __fdividef(refined, 1.0f + __expf(fmaf(p.z, 50.0f, -50.0f)));
    r.w = __fdividef(refined, 1.0f + __expf(fmaf(p.w, 50.0f, -50.0f)));
    reinterpret_cast<float4*>(out)[i] = r;
}

extern "C" void kernel_launch(void* const* d_in, const int* in_sizes, int n_in,
                              void* d_out, int out_size) {
    const float* psi_n   = (const float*)d_in[2];
    const float* ln_bias = (const float*)d_in[25];
    float* out = (float*)d_out;

    int n4 = out_size / 4;          // 16384
    int blocks = n4 / 128;          // 128 CTAs x 128 threads, exact cover
    collapsed_forward_kernel<<<blocks, 128>>>(psi_n, ln_bias, out);
}